// round 4
// baseline (speedup 1.0000x reference)
#include <cuda_runtime.h>
#include <cstdint>

#define BSZ 32
#define CNT 128
#define Wd  2048
#define Pd  1024
#define Ed  8
#define Kc  25
#define Ld  2
#define ROWS (BSZ*CNT)   // 4096

// ---------------- scratch ----------------
__device__ float g_x[ROWS*Wd];            // inter-layer activation
__device__ float g_chi[ROWS*Wd];          // conv out, tf32 hi
__device__ float g_clo[ROWS*Wd];          // conv out, tf32 lo
__device__ float g_qkv[3*ROWS*Pd];        // q,k,v outputs (z-strided)
__device__ float g_phi[ROWS*Pd];
__device__ float g_plo[ROWS*Pd];
__device__ float g_wqkvhi[3*Ld*Pd*Wd];    // [matrix z][layer][P][W]
__device__ float g_wqkvlo[3*Ld*Pd*Wd];
__device__ float g_wohi[Ld*Wd*Pd];
__device__ float g_wolo[Ld*Wd*Pd];
__device__ float g_bqkv[3*Ld*Pd];
__device__ float g_wavg[Ld*Kc];
__device__ float g_bavg[Ld];

__device__ __forceinline__ uint32_t f2tf32(float x) {
    uint32_t r;
    asm("cvt.rna.tf32.f32 %0, %1;" : "=r"(r) : "f"(x));
    return r;
}
__device__ __forceinline__ uint32_t smem_u32(const void* p) {
    uint32_t a;
    asm("{ .reg .u64 t; cvta.to.shared.u64 t, %1; cvt.u32.u64 %0, t; }" : "=r"(a) : "l"(p));
    return a;
}
__device__ __forceinline__ void cp16(uint32_t dst, const float* src) {
    asm volatile("cp.async.cg.shared.global [%0], [%1], 16;" :: "r"(dst), "l"(src));
}

// ---------------- weight split (fp32 -> tf32 hi/lo) ----------------
__global__ void split_kernel(const float* __restrict__ src, float* __restrict__ hi,
                             float* __restrict__ lo, int n4) {
    int i = blockIdx.x * blockDim.x + threadIdx.x;
    int stride = gridDim.x * blockDim.x;
    for (; i < n4; i += stride) {
        float4 v = ((const float4*)src)[i];
        float4 h, l;
        uint32_t u;
        u = f2tf32(v.x); h.x = __uint_as_float(u); l.x = __uint_as_float(f2tf32(v.x - h.x));
        u = f2tf32(v.y); h.y = __uint_as_float(u); l.y = __uint_as_float(f2tf32(v.y - h.y));
        u = f2tf32(v.z); h.z = __uint_as_float(u); l.z = __uint_as_float(f2tf32(v.z - h.z));
        u = f2tf32(v.w); h.w = __uint_as_float(u); l.w = __uint_as_float(f2tf32(v.w - h.w));
        ((float4*)hi)[i] = h;
        ((float4*)lo)[i] = l;
    }
}

// ---------------- avg conv weights ----------------
__global__ void avg_conv_kernel(const float* __restrict__ cw, const float* __restrict__ cb,
                                float* __restrict__ wavg, float* __restrict__ bavg) {
    int idx = threadIdx.x;
    if (idx < Ld * Kc) {
        int l = idx / Kc, kk = idx % Kc;
        float s = 0.f;
        #pragma unroll
        for (int e = 0; e < Ed; e++) s += cw[(l * Ed + e) * Kc + kk];
        wavg[idx] = s * (1.0f / Ed);
    }
    if (idx < Ld) {
        float s = 0.f;
        #pragma unroll
        for (int e = 0; e < Ed; e++) s += cb[idx * Ed + e];
        bavg[idx] = s * (1.0f / Ed);
    }
}

// ---------------- 1D conv, writes tf32 hi/lo ----------------
__global__ __launch_bounds__(256) void conv_row_kernel(
    const float* __restrict__ X, float* __restrict__ Yhi, float* __restrict__ Ylo,
    const float* __restrict__ wavg, const float* __restrict__ bavg)
{
    __shared__ float sx[Wd + Kc - 1];
    __shared__ float wsh[Kc];
    const int row = blockIdx.x;
    const int tid = threadIdx.x;
    const float* xr = X + (size_t)row * Wd;

    for (int i = tid; i < Wd + Kc - 1; i += 256) {
        int src = i - (Kc / 2);
        sx[i] = (src >= 0 && src < Wd) ? xr[src] : 0.0f;
    }
    if (tid < Kc) wsh[tid] = wavg[tid];
    __syncthreads();

    const float b = bavg[0];
    float* yh = Yhi + (size_t)row * Wd;
    float* yl = Ylo + (size_t)row * Wd;
    for (int h = tid; h < Wd; h += 256) {
        float s = b;
        #pragma unroll
        for (int k = 0; k < Kc; k++) s += sx[h + k] * wsh[k];
        float shi = __uint_as_float(f2tf32(s));
        yh[h] = shi;
        yl[h] = __uint_as_float(f2tf32(s - shi));
    }
}

// ---------------- 3xTF32 mma.sync GEMM, cp.async 3-stage pipeline ----------------
#define MMA8(cc, aa, bb) \
    asm volatile("mma.sync.aligned.m16n8k8.row.col.f32.tf32.tf32.f32 " \
        "{%0,%1,%2,%3},{%4,%5,%6,%7},{%8,%9},{%0,%1,%2,%3};" \
        : "+f"((cc)[0]), "+f"((cc)[1]), "+f"((cc)[2]), "+f"((cc)[3]) \
        : "r"((aa)[0]), "r"((aa)[1]), "r"((aa)[2]), "r"((aa)[3]), \
          "r"((bb)[0]), "r"((bb)[1]))

#define BK 32
#define TILE_F 4096            // 128x32 floats, swizzled (no pad)
#define STAGE_F (4*TILE_F)     // Ahi, Alo, Bhi, Blo
#define NSTAGE 3
#define GEMM_SMEM (NSTAGE*STAGE_F*4)   // 196608 bytes

__global__ __launch_bounds__(512, 1) void gemm_mma_kernel(
    const float* __restrict__ Ahi, const float* __restrict__ Alo,
    const float* __restrict__ Bhi, const float* __restrict__ Blo,
    const float* __restrict__ bias, float* __restrict__ C,
    int Kd, int N, size_t szB, size_t szBias, size_t szC)
{
    extern __shared__ uint32_t sm[];
    const uint32_t sbase = smem_u32(sm);
    const int z = blockIdx.z;
    Bhi  += (size_t)z * szB;
    Blo  += (size_t)z * szB;
    bias += (size_t)z * szBias;
    C    += (size_t)z * szC;

    const int tid = threadIdx.x;
    const int wid = tid >> 5, lane = tid & 31;
    const int g = lane >> 2, t = lane & 3;
    const int wm = (wid >> 2) * 32;
    const int wn = (wid & 3) * 32;
    const int bm = blockIdx.y * 128, bn = blockIdx.x * 128;

    // cp.async mapping: row = tid>>2 (0..127), two 16B groups per tile
    const int lrow = tid >> 2;
    const int gsel = tid & 3;
    const float* pAhi = Ahi + (size_t)(bm + lrow) * Kd;
    const float* pAlo = Alo + (size_t)(bm + lrow) * Kd;
    const float* pBhi = Bhi + (size_t)(bn + lrow) * Kd;
    const float* pBlo = Blo + (size_t)(bn + lrow) * Kd;
    const int c0 = gsel * 4, c1 = (gsel + 4) * 4;
    const uint32_t xr = (uint32_t)((lrow & 7) * 4);
    const uint32_t d0 = (uint32_t)(lrow * 32) + ((uint32_t)c0 ^ xr);
    const uint32_t d1 = (uint32_t)(lrow * 32) + ((uint32_t)c1 ^ xr);

    float acc[2][4][4];
    #pragma unroll
    for (int mt = 0; mt < 2; mt++)
        #pragma unroll
        for (int nt = 0; nt < 4; nt++)
            #pragma unroll
            for (int e = 0; e < 4; e++) acc[mt][nt][e] = 0.0f;

    const int NC = Kd / BK;

    // pipeline issue helper (macro to keep pointers in regs)
    #define ISSUE(s, kpos) do { \
        uint32_t _sb = sbase + (uint32_t)(s) * (STAGE_F * 4); \
        cp16(_sb + d0 * 4,                   pAhi + (kpos) + c0); \
        cp16(_sb + d1 * 4,                   pAhi + (kpos) + c1); \
        cp16(_sb + (TILE_F + d0) * 4,        pAlo + (kpos) + c0); \
        cp16(_sb + (TILE_F + d1) * 4,        pAlo + (kpos) + c1); \
        cp16(_sb + (2 * TILE_F + d0) * 4,    pBhi + (kpos) + c0); \
        cp16(_sb + (2 * TILE_F + d1) * 4,    pBhi + (kpos) + c1); \
        cp16(_sb + (3 * TILE_F + d0) * 4,    pBlo + (kpos) + c0); \
        cp16(_sb + (3 * TILE_F + d1) * 4,    pBlo + (kpos) + c1); \
        asm volatile("cp.async.commit_group;" ::: "memory"); \
    } while (0)

    ISSUE(0, 0);
    ISSUE(1, BK);

    const uint32_t xg = (uint32_t)(g * 4);

    for (int i = 0; i < NC; i++) {
        if (i + 1 < NC) asm volatile("cp.async.wait_group 1;" ::: "memory");
        else            asm volatile("cp.async.wait_group 0;" ::: "memory");
        __syncthreads();
        if (i + 2 < NC) {
            int s = i + 2; s = s - (s / 3) * 3;
            ISSUE(s, (i + 2) * BK);
        }

        int bsel = i - (i / 3) * 3;
        const uint32_t* sAh = sm + bsel * STAGE_F;
        const uint32_t* sAl = sAh + TILE_F;
        const uint32_t* sBh = sAl + TILE_F;
        const uint32_t* sBl = sBh + TILE_F;

        #pragma unroll
        for (int ks = 0; ks < 4; ks++) {
            const uint32_t kk = ks * 8;
            uint32_t ah[2][4], al[2][4], bh[4][2], bl[4][2];
            #pragma unroll
            for (int mt = 0; mt < 2; mt++) {
                int r = wm + mt * 16 + g;
                int i0 = r * 32 + (int)((kk) ^ xg) + t;
                int i4 = r * 32 + (int)((kk + 4) ^ xg) + t;
                ah[mt][0] = sAh[i0]; ah[mt][1] = sAh[i0 + 256];
                ah[mt][2] = sAh[i4]; ah[mt][3] = sAh[i4 + 256];
                al[mt][0] = sAl[i0]; al[mt][1] = sAl[i0 + 256];
                al[mt][2] = sAl[i4]; al[mt][3] = sAl[i4 + 256];
            }
            #pragma unroll
            for (int nt = 0; nt < 4; nt++) {
                int r = wn + nt * 8 + g;
                int i0 = r * 32 + (int)((kk) ^ xg) + t;
                int i4 = r * 32 + (int)((kk + 4) ^ xg) + t;
                bh[nt][0] = sBh[i0]; bh[nt][1] = sBh[i4];
                bl[nt][0] = sBl[i0]; bl[nt][1] = sBl[i4];
            }
            #pragma unroll
            for (int mt = 0; mt < 2; mt++)
                #pragma unroll
                for (int nt = 0; nt < 4; nt++) {
                    MMA8(acc[mt][nt], ah[mt], bh[nt]);
                    MMA8(acc[mt][nt], al[mt], bh[nt]);
                    MMA8(acc[mt][nt], ah[mt], bl[nt]);
                }
        }
        __syncthreads();
    }
    #undef ISSUE

    // epilogue
    #pragma unroll
    for (int mt = 0; mt < 2; mt++) {
        #pragma unroll
        for (int nt = 0; nt < 4; nt++) {
            int col = bn + wn + nt * 8 + 2 * t;
            float b0 = __ldg(&bias[col]);
            float b1 = __ldg(&bias[col + 1]);
            float* p0 = C + (size_t)(bm + wm + mt * 16 + g) * N + col;
            float2 o0 = make_float2(acc[mt][nt][0] + b0, acc[mt][nt][1] + b1);
            float2 o1 = make_float2(acc[mt][nt][2] + b0, acc[mt][nt][3] + b1);
            *(float2*)p0 = o0;
            *(float2*)(p0 + 8 * N) = o1;
        }
    }
}

// ---------------- FFT attention (writes p hi/lo) ----------------
__device__ __forceinline__ void fft1024_stages(float2* s, int tid, float sign) {
    #pragma unroll
    for (int stage = 0; stage < 10; ++stage) {
        const int half = 1 << stage;
        #pragma unroll
        for (int r = 0; r < 2; ++r) {
            int b = tid + (r << 8);
            int pos = b & (half - 1);
            int i0 = ((b >> stage) << (stage + 1)) + pos;
            int i1 = i0 + half;
            float ang = sign * 3.14159265358979323846f * (float)pos / (float)half;
            float sn, cs;
            __sincosf(ang, &sn, &cs);
            float2 x1 = s[i1];
            float2 t = make_float2(x1.x * cs - x1.y * sn, x1.x * sn + x1.y * cs);
            float2 x0 = s[i0];
            s[i0] = make_float2(x0.x + t.x, x0.y + t.y);
            s[i1] = make_float2(x0.x - t.x, x0.y - t.y);
        }
        __syncthreads();
    }
}

__global__ __launch_bounds__(256) void fft_attn_kernel(
    const float* __restrict__ Q, const float* __restrict__ Kx,
    const float* __restrict__ V, float* __restrict__ Ohi, float* __restrict__ Olo)
{
    __shared__ float2 Z[1024];
    __shared__ float2 Aw[1024];
    const int row = blockIdx.x;
    const int tid = threadIdx.x;
    const float* qr = Q  + (size_t)row * Pd;
    const float* kr = Kx + (size_t)row * Pd;
    const float* vr = V  + (size_t)row * Pd;

    for (int i = tid; i < 1024; i += 256) {
        int rdx = __brev((unsigned)i) >> 22;
        Z[rdx] = make_float2(qr[i], kr[i]);
    }
    __syncthreads();
    fft1024_stages(Z, tid, -1.0f);

    const float inv_scale = 1.0f / 32.0f;
    for (int i = tid; i < 1024; i += 256) {
        float2 zj = Z[i];
        float2 zn = Z[(1024 - i) & 1023];
        float Qx = 0.5f * (zj.x + zn.x);
        float Qy = 0.5f * (zj.y - zn.y);
        float Kxr = 0.5f * (zj.y + zn.y);
        float Kyr = -0.5f * (zj.x - zn.x);
        float Ax = Kxr * Qx + Kyr * Qy;
        float Ay = Kyr * Qx - Kxr * Qy;
        Aw[i] = make_float2(Ax * inv_scale, Ay * inv_scale);
    }
    __syncthreads();

    for (int i = tid; i < 1024; i += 256) {
        int rdx = __brev((unsigned)i) >> 22;
        Z[rdx] = make_float2(vr[i], 0.0f);
    }
    __syncthreads();
    fft1024_stages(Z, tid, -1.0f);

    for (int i = tid; i < 1024; i += 256) {
        float2 vf = Z[i], a = Aw[i];
        Aw[i] = make_float2(vf.x * a.x - vf.y * a.y, vf.x * a.y + vf.y * a.x);
    }
    __syncthreads();

    for (int i = tid; i < 1024; i += 256) {
        int rdx = __brev((unsigned)i) >> 22;
        Z[rdx] = Aw[i];
    }
    __syncthreads();
    fft1024_stages(Z, tid, +1.0f);

    float* oh = Ohi + (size_t)row * Pd;
    float* ol = Olo + (size_t)row * Pd;
    const float invN = 1.0f / 1024.0f;
    for (int i = tid; i < 1024; i += 256) {
        float s = Z[i].x * invN;
        float shi = __uint_as_float(f2tf32(s));
        oh[i] = shi;
        ol[i] = __uint_as_float(f2tf32(s - shi));
    }
}

// ---------------- launch ----------------
extern "C" void kernel_launch(void* const* d_in, const int* in_sizes, int n_in,
                              void* d_out, int out_size) {
    (void)in_sizes; (void)n_in; (void)out_size;
    const float* x      = (const float*)d_in[0];
    const float* conv_w = (const float*)d_in[1];
    const float* conv_b = (const float*)d_in[2];
    const float* wq     = (const float*)d_in[3];
    const float* bq     = (const float*)d_in[4];
    const float* wk     = (const float*)d_in[5];
    const float* bk     = (const float*)d_in[6];
    const float* wv     = (const float*)d_in[7];
    const float* bv     = (const float*)d_in[8];
    const float* wo     = (const float*)d_in[9];
    const float* bo     = (const float*)d_in[10];
    float* out = (float*)d_out;

    float *xb, *chi, *clo, *qkv, *phi, *plo;
    float *wqkvhi, *wqkvlo, *wohi, *wolo, *bqkv, *wavg, *bavg;
    cudaGetSymbolAddress((void**)&xb,     g_x);
    cudaGetSymbolAddress((void**)&chi,    g_chi);
    cudaGetSymbolAddress((void**)&clo,    g_clo);
    cudaGetSymbolAddress((void**)&qkv,    g_qkv);
    cudaGetSymbolAddress((void**)&phi,    g_phi);
    cudaGetSymbolAddress((void**)&plo,    g_plo);
    cudaGetSymbolAddress((void**)&wqkvhi, g_wqkvhi);
    cudaGetSymbolAddress((void**)&wqkvlo, g_wqkvlo);
    cudaGetSymbolAddress((void**)&wohi,   g_wohi);
    cudaGetSymbolAddress((void**)&wolo,   g_wolo);
    cudaGetSymbolAddress((void**)&bqkv,   g_bqkv);
    cudaGetSymbolAddress((void**)&wavg,   g_wavg);
    cudaGetSymbolAddress((void**)&bavg,   g_bavg);

    cudaFuncSetAttribute(gemm_mma_kernel,
                         cudaFuncAttributeMaxDynamicSharedMemorySize, GEMM_SMEM);

    const size_t LPW = (size_t)Ld * Pd * Wd;   // 4M elements

    avg_conv_kernel<<<1, 64>>>(conv_w, conv_b, wavg, bavg);

    // weight splits (once per launch)
    split_kernel<<<2048, 256>>>(wq, wqkvhi,           wqkvlo,           (int)(LPW / 4));
    split_kernel<<<2048, 256>>>(wk, wqkvhi + LPW,     wqkvlo + LPW,     (int)(LPW / 4));
    split_kernel<<<2048, 256>>>(wv, wqkvhi + 2 * LPW, wqkvlo + 2 * LPW, (int)(LPW / 4));
    split_kernel<<<2048, 256>>>(wo, wohi,             wolo,             (int)(LPW / 4));

    // bias concat (z-strided): g_bqkv[z][l][p]
    cudaMemcpyAsync(bqkv,               bq, Ld * Pd * 4, cudaMemcpyDeviceToDevice);
    cudaMemcpyAsync(bqkv + Ld * Pd,     bk, Ld * Pd * 4, cudaMemcpyDeviceToDevice);
    cudaMemcpyAsync(bqkv + 2 * Ld * Pd, bv, Ld * Pd * 4, cudaMemcpyDeviceToDevice);

    const size_t RP = (size_t)ROWS * Pd;

    for (int l = 0; l < Ld; l++) {
        const float* xin = (l == 0) ? x : xb;
        float* xout = (l == Ld - 1) ? out : xb;

        conv_row_kernel<<<ROWS, 256>>>(xin, chi, clo, wavg + l * Kc, bavg + l);

        // fused q/k/v: grid z selects weight/bias/output
        dim3 gq(Pd / 128, ROWS / 128, 3);
        gemm_mma_kernel<<<gq, 512, GEMM_SMEM>>>(
            chi, clo,
            wqkvhi + (size_t)l * Pd * Wd, wqkvlo + (size_t)l * Pd * Wd,
            bqkv + (size_t)l * Pd, qkv,
            Wd, Pd, LPW, (size_t)Ld * Pd, RP);

        fft_attn_kernel<<<ROWS, 256>>>(qkv, qkv + RP, qkv + 2 * RP, phi, plo);

        dim3 go(Wd / 128, ROWS / 128, 1);
        gemm_mma_kernel<<<go, 512, GEMM_SMEM>>>(
            phi, plo,
            wohi + (size_t)l * Wd * Pd, wolo + (size_t)l * Wd * Pd,
            bo + (size_t)l * Wd, xout,
            Pd, Wd, 0, 0, 0);
    }
}

// round 5
// speedup vs baseline: 1.0682x; 1.0682x over previous
#include <cuda_runtime.h>
#include <cuda_bf16.h>
#include <cstdint>

#define BSZ 32
#define CNT 128
#define Wd  2048
#define Pd  1024
#define Ed  8
#define Kc  25
#define Ld  2
#define ROWS (BSZ*CNT)   // 4096

typedef __nv_bfloat16 bf16;

// ---------------- scratch ----------------
__device__ float g_x[ROWS*Wd];                 // inter-layer activation (fp32)
__device__ bf16  g_ch[ROWS*Wd];                // conv out, bf16 h/m/l
__device__ bf16  g_cm[ROWS*Wd];
__device__ bf16  g_cl[ROWS*Wd];
__device__ float g_qkv[3*ROWS*Pd];             // q,k,v (fp32, z-strided)
__device__ bf16  g_ph[ROWS*Pd];
__device__ bf16  g_pm[ROWS*Pd];
__device__ bf16  g_pl[ROWS*Pd];
__device__ bf16  g_wqkvh[3*Ld*Pd*Wd];          // [z][layer][P][W]
__device__ bf16  g_wqkvm[3*Ld*Pd*Wd];
__device__ bf16  g_wqkvl[3*Ld*Pd*Wd];
__device__ bf16  g_woh[Ld*Wd*Pd];
__device__ bf16  g_wom[Ld*Wd*Pd];
__device__ bf16  g_wol[Ld*Wd*Pd];
__device__ float g_bqkv[3*Ld*Pd];
__device__ float g_wavg[Ld*Kc];
__device__ float g_bavg[Ld];

// ---------------- helpers ----------------
__device__ __forceinline__ uint32_t smem_u32(const void* p) {
    uint32_t a;
    asm("{ .reg .u64 t; cvta.to.shared.u64 t, %1; cvt.u32.u64 %0, t; }" : "=r"(a) : "l"(p));
    return a;
}
__device__ __forceinline__ void cp16(uint32_t dst, const void* src) {
    asm volatile("cp.async.cg.shared.global [%0], [%1], 16;" :: "r"(dst), "l"(src));
}
__device__ __forceinline__ void split3(float x, bf16& h, bf16& m, bf16& l) {
    h = __float2bfloat16(x);
    float r1 = x - __bfloat162float(h);
    m = __float2bfloat16(r1);
    l = __float2bfloat16(r1 - __bfloat162float(m));
}
__device__ __forceinline__ uint32_t pack2(bf16 a, bf16 b) {
    return (uint32_t)__bfloat16_as_ushort(a) | ((uint32_t)__bfloat16_as_ushort(b) << 16);
}

// ---------------- weight split fp32 -> 3x bf16 ----------------
__global__ void split3_kernel(const float* __restrict__ src, bf16* __restrict__ h,
                              bf16* __restrict__ m, bf16* __restrict__ l, int n8) {
    int i = blockIdx.x * blockDim.x + threadIdx.x;
    int stride = gridDim.x * blockDim.x;
    for (; i < n8; i += stride) {
        float4 v0 = ((const float4*)src)[2 * i];
        float4 v1 = ((const float4*)src)[2 * i + 1];
        float v[8] = {v0.x, v0.y, v0.z, v0.w, v1.x, v1.y, v1.z, v1.w};
        bf16 hh[8], mm_[8], ll[8];
        #pragma unroll
        for (int e = 0; e < 8; e++) split3(v[e], hh[e], mm_[e], ll[e]);
        uint4 u;
        u.x = pack2(hh[0], hh[1]); u.y = pack2(hh[2], hh[3]);
        u.z = pack2(hh[4], hh[5]); u.w = pack2(hh[6], hh[7]);
        ((uint4*)h)[i] = u;
        u.x = pack2(mm_[0], mm_[1]); u.y = pack2(mm_[2], mm_[3]);
        u.z = pack2(mm_[4], mm_[5]); u.w = pack2(mm_[6], mm_[7]);
        ((uint4*)m)[i] = u;
        u.x = pack2(ll[0], ll[1]); u.y = pack2(ll[2], ll[3]);
        u.z = pack2(ll[4], ll[5]); u.w = pack2(ll[6], ll[7]);
        ((uint4*)l)[i] = u;
    }
}

// ---------------- avg conv weights ----------------
__global__ void avg_conv_kernel(const float* __restrict__ cw, const float* __restrict__ cb,
                                float* __restrict__ wavg, float* __restrict__ bavg) {
    int idx = threadIdx.x;
    if (idx < Ld * Kc) {
        int l = idx / Kc, kk = idx % Kc;
        float s = 0.f;
        #pragma unroll
        for (int e = 0; e < Ed; e++) s += cw[(l * Ed + e) * Kc + kk];
        wavg[idx] = s * (1.0f / Ed);
    }
    if (idx < Ld) {
        float s = 0.f;
        #pragma unroll
        for (int e = 0; e < Ed; e++) s += cb[idx * Ed + e];
        bavg[idx] = s * (1.0f / Ed);
    }
}

// ---------------- 1D conv, writes 3x bf16 ----------------
__global__ __launch_bounds__(256) void conv_row_kernel(
    const float* __restrict__ X, bf16* __restrict__ Yh, bf16* __restrict__ Ym,
    bf16* __restrict__ Yl, const float* __restrict__ wavg, const float* __restrict__ bavg)
{
    __shared__ float sx[Wd + Kc - 1];
    __shared__ float wsh[Kc];
    const int row = blockIdx.x;
    const int tid = threadIdx.x;
    const float* xr = X + (size_t)row * Wd;

    for (int i = tid; i < Wd + Kc - 1; i += 256) {
        int src = i - (Kc / 2);
        sx[i] = (src >= 0 && src < Wd) ? xr[src] : 0.0f;
    }
    if (tid < Kc) wsh[tid] = wavg[tid];
    __syncthreads();

    const float b = bavg[0];
    bf16* yh = Yh + (size_t)row * Wd;
    bf16* ym = Ym + (size_t)row * Wd;
    bf16* yl = Yl + (size_t)row * Wd;
    for (int h = tid; h < Wd; h += 256) {
        float s = b;
        #pragma unroll
        for (int k = 0; k < Kc; k++) s += sx[h + k] * wsh[k];
        bf16 sh, sm_, sl;
        split3(s, sh, sm_, sl);
        yh[h] = sh; ym[h] = sm_; yl[h] = sl;
    }
}

// ---------------- bf16x6 mma.sync GEMM: C = A*B^T + bias ----------------
#define MMA16(cc, aa, bb) \
    asm volatile("mma.sync.aligned.m16n8k16.row.col.f32.bf16.bf16.f32 " \
        "{%0,%1,%2,%3},{%4,%5,%6,%7},{%8,%9},{%0,%1,%2,%3};" \
        : "+f"((cc)[0]), "+f"((cc)[1]), "+f"((cc)[2]), "+f"((cc)[3]) \
        : "r"((aa)[0]), "r"((aa)[1]), "r"((aa)[2]), "r"((aa)[3]), \
          "r"((bb)[0]), "r"((bb)[1]))

#define BK 32
#define TILE_W 2048            // 128 rows x 16 words (32 bf16), swizzled
#define STAGE_W (6*TILE_W)     // Ah,Am,Al,Bh,Bm,Bl
#define NSTAGE 3
#define GEMM_SMEM (NSTAGE*STAGE_W*4)   // 147456 bytes

__global__ __launch_bounds__(512, 1) void gemm_mma_kernel(
    const bf16* __restrict__ Ah, const bf16* __restrict__ Am, const bf16* __restrict__ Al,
    const bf16* __restrict__ Bh, const bf16* __restrict__ Bm, const bf16* __restrict__ Bl,
    const float* __restrict__ bias, float* __restrict__ C,
    int Kd, int N, size_t szB, size_t szBias, size_t szC)
{
    extern __shared__ uint32_t sm[];
    const uint32_t sbase = smem_u32(sm);
    const int z = blockIdx.z;
    Bh   += (size_t)z * szB;
    Bm   += (size_t)z * szB;
    Bl   += (size_t)z * szB;
    bias += (size_t)z * szBias;
    C    += (size_t)z * szC;

    const int tid = threadIdx.x;
    const int wid = tid >> 5, lane = tid & 31;
    const int g = lane >> 2, t = lane & 3;
    const int wm = (wid >> 2) * 32;
    const int wn = (wid & 3) * 32;
    const int bm = blockIdx.y * 128, bn = blockIdx.x * 128;

    // cp.async mapping: one 16B transfer per tile per thread
    const int lrow = tid >> 2;          // 0..127
    const int c4 = tid & 3;             // 16B group within row
    const int sg = c4 ^ ((lrow >> 1) & 3);
    const uint32_t dstw = (uint32_t)(lrow * 16 + sg * 4);   // word index in tile

    const bf16* pAh = Ah + (size_t)(bm + lrow) * Kd + c4 * 8;
    const bf16* pAm = Am + (size_t)(bm + lrow) * Kd + c4 * 8;
    const bf16* pAl = Al + (size_t)(bm + lrow) * Kd + c4 * 8;
    const bf16* pBh = Bh + (size_t)(bn + lrow) * Kd + c4 * 8;
    const bf16* pBm = Bm + (size_t)(bn + lrow) * Kd + c4 * 8;
    const bf16* pBl = Bl + (size_t)(bn + lrow) * Kd + c4 * 8;

    float acc[2][4][4];
    #pragma unroll
    for (int mt = 0; mt < 2; mt++)
        #pragma unroll
        for (int nt = 0; nt < 4; nt++)
            #pragma unroll
            for (int e = 0; e < 4; e++) acc[mt][nt][e] = 0.0f;

    const int NC = Kd / BK;

    #define ISSUE(s, kpos) do { \
        uint32_t _sb = sbase + (uint32_t)(s) * (STAGE_W * 4) + dstw * 4; \
        cp16(_sb,                   pAh + (kpos)); \
        cp16(_sb + TILE_W * 4,      pAm + (kpos)); \
        cp16(_sb + 2 * TILE_W * 4,  pAl + (kpos)); \
        cp16(_sb + 3 * TILE_W * 4,  pBh + (kpos)); \
        cp16(_sb + 4 * TILE_W * 4,  pBm + (kpos)); \
        cp16(_sb + 5 * TILE_W * 4,  pBl + (kpos)); \
        asm volatile("cp.async.commit_group;" ::: "memory"); \
    } while (0)

    ISSUE(0, 0);
    ISSUE(1, BK);

    for (int i = 0; i < NC; i++) {
        if (i + 1 < NC) asm volatile("cp.async.wait_group 1;" ::: "memory");
        else            asm volatile("cp.async.wait_group 0;" ::: "memory");
        __syncthreads();
        if (i + 2 < NC) {
            int s = i + 2; s = s - (s / 3) * 3;
            ISSUE(s, (i + 2) * BK);
        }

        int bsel = i - (i / 3) * 3;
        const uint32_t* sAh = sm + bsel * STAGE_W;
        const uint32_t* sAm = sAh + TILE_W;
        const uint32_t* sAl = sAm + TILE_W;
        const uint32_t* sBh = sAl + TILE_W;
        const uint32_t* sBm = sBh + TILE_W;
        const uint32_t* sBl = sBm + TILE_W;

        #pragma unroll
        for (int st = 0; st < 2; st++) {
            const int kb = st * 8;            // word-col base (w&12 part)
            uint32_t ah[2][4], am_[2][4], al_[2][4];
            uint32_t bh[4][2], bmr[4][2], blr[4][2];
            #pragma unroll
            for (int mt = 0; mt < 2; mt++) {
                int r0 = wm + mt * 16 + g;
                int rx = ((r0 >> 1) & 3) << 2;        // same for r0 and r0+8
                int i0 = r0 * 16 + (kb ^ rx) + t;
                int i4 = r0 * 16 + ((kb + 4) ^ rx) + t;
                ah[mt][0] = sAh[i0]; ah[mt][1] = sAh[i0 + 128];
                ah[mt][2] = sAh[i4]; ah[mt][3] = sAh[i4 + 128];
                am_[mt][0] = sAm[i0]; am_[mt][1] = sAm[i0 + 128];
                am_[mt][2] = sAm[i4]; am_[mt][3] = sAm[i4 + 128];
                al_[mt][0] = sAl[i0]; al_[mt][1] = sAl[i0 + 128];
                al_[mt][2] = sAl[i4]; al_[mt][3] = sAl[i4 + 128];
            }
            #pragma unroll
            for (int nt = 0; nt < 4; nt++) {
                int rb = wn + nt * 8 + g;
                int rx = ((rb >> 1) & 3) << 2;
                int i0 = rb * 16 + (kb ^ rx) + t;
                int i4 = rb * 16 + ((kb + 4) ^ rx) + t;
                bh[nt][0]  = sBh[i0]; bh[nt][1]  = sBh[i4];
                bmr[nt][0] = sBm[i0]; bmr[nt][1] = sBm[i4];
                blr[nt][0] = sBl[i0]; blr[nt][1] = sBl[i4];
            }
            #pragma unroll
            for (int mt = 0; mt < 2; mt++)
                #pragma unroll
                for (int nt = 0; nt < 4; nt++) {
                    MMA16(acc[mt][nt], ah[mt],  bh[nt]);
                    MMA16(acc[mt][nt], ah[mt],  bmr[nt]);
                    MMA16(acc[mt][nt], am_[mt], bh[nt]);
                    MMA16(acc[mt][nt], ah[mt],  blr[nt]);
                    MMA16(acc[mt][nt], al_[mt], bh[nt]);
                    MMA16(acc[mt][nt], am_[mt], bmr[nt]);
                }
        }
        __syncthreads();
    }
    #undef ISSUE

    // epilogue
    #pragma unroll
    for (int mt = 0; mt < 2; mt++) {
        #pragma unroll
        for (int nt = 0; nt < 4; nt++) {
            int col = bn + wn + nt * 8 + 2 * t;
            float b0 = __ldg(&bias[col]);
            float b1 = __ldg(&bias[col + 1]);
            float* p0 = C + (size_t)(bm + wm + mt * 16 + g) * N + col;
            float2 o0 = make_float2(acc[mt][nt][0] + b0, acc[mt][nt][1] + b1);
            float2 o1 = make_float2(acc[mt][nt][2] + b0, acc[mt][nt][3] + b1);
            *(float2*)p0 = o0;
            *(float2*)(p0 + 8 * N) = o1;
        }
    }
}

// ---------------- FFT attention (writes 3x bf16) ----------------
__device__ __forceinline__ void fft1024_stages(float2* s, int tid, float sign) {
    #pragma unroll
    for (int stage = 0; stage < 10; ++stage) {
        const int half = 1 << stage;
        #pragma unroll
        for (int r = 0; r < 2; ++r) {
            int b = tid + (r << 8);
            int pos = b & (half - 1);
            int i0 = ((b >> stage) << (stage + 1)) + pos;
            int i1 = i0 + half;
            float ang = sign * 3.14159265358979323846f * (float)pos / (float)half;
            float sn, cs;
            __sincosf(ang, &sn, &cs);
            float2 x1 = s[i1];
            float2 t = make_float2(x1.x * cs - x1.y * sn, x1.x * sn + x1.y * cs);
            float2 x0 = s[i0];
            s[i0] = make_float2(x0.x + t.x, x0.y + t.y);
            s[i1] = make_float2(x0.x - t.x, x0.y - t.y);
        }
        __syncthreads();
    }
}

__global__ __launch_bounds__(256) void fft_attn_kernel(
    const float* __restrict__ Q, const float* __restrict__ Kx,
    const float* __restrict__ V,
    bf16* __restrict__ Oh, bf16* __restrict__ Om, bf16* __restrict__ Ol)
{
    __shared__ float2 Z[1024];
    __shared__ float2 Aw[1024];
    const int row = blockIdx.x;
    const int tid = threadIdx.x;
    const float* qr = Q  + (size_t)row * Pd;
    const float* kr = Kx + (size_t)row * Pd;
    const float* vr = V  + (size_t)row * Pd;

    for (int i = tid; i < 1024; i += 256) {
        int rdx = __brev((unsigned)i) >> 22;
        Z[rdx] = make_float2(qr[i], kr[i]);
    }
    __syncthreads();
    fft1024_stages(Z, tid, -1.0f);

    const float inv_scale = 1.0f / 32.0f;
    for (int i = tid; i < 1024; i += 256) {
        float2 zj = Z[i];
        float2 zn = Z[(1024 - i) & 1023];
        float Qx = 0.5f * (zj.x + zn.x);
        float Qy = 0.5f * (zj.y - zn.y);
        float Kxr = 0.5f * (zj.y + zn.y);
        float Kyr = -0.5f * (zj.x - zn.x);
        float Ax = Kxr * Qx + Kyr * Qy;
        float Ay = Kyr * Qx - Kxr * Qy;
        Aw[i] = make_float2(Ax * inv_scale, Ay * inv_scale);
    }
    __syncthreads();

    for (int i = tid; i < 1024; i += 256) {
        int rdx = __brev((unsigned)i) >> 22;
        Z[rdx] = make_float2(vr[i], 0.0f);
    }
    __syncthreads();
    fft1024_stages(Z, tid, -1.0f);

    for (int i = tid; i < 1024; i += 256) {
        float2 vf = Z[i], a = Aw[i];
        Aw[i] = make_float2(vf.x * a.x - vf.y * a.y, vf.x * a.y + vf.y * a.x);
    }
    __syncthreads();

    for (int i = tid; i < 1024; i += 256) {
        int rdx = __brev((unsigned)i) >> 22;
        Z[rdx] = Aw[i];
    }
    __syncthreads();
    fft1024_stages(Z, tid, +1.0f);

    bf16* oh = Oh + (size_t)row * Pd;
    bf16* om = Om + (size_t)row * Pd;
    bf16* ol = Ol + (size_t)row * Pd;
    const float invN = 1.0f / 1024.0f;
    for (int i = tid; i < 1024; i += 256) {
        float s = Z[i].x * invN;
        bf16 sh, sm_, sl;
        split3(s, sh, sm_, sl);
        oh[i] = sh; om[i] = sm_; ol[i] = sl;
    }
}

// ---------------- launch ----------------
extern "C" void kernel_launch(void* const* d_in, const int* in_sizes, int n_in,
                              void* d_out, int out_size) {
    (void)in_sizes; (void)n_in; (void)out_size;
    const float* x      = (const float*)d_in[0];
    const float* conv_w = (const float*)d_in[1];
    const float* conv_b = (const float*)d_in[2];
    const float* wq     = (const float*)d_in[3];
    const float* bq     = (const float*)d_in[4];
    const float* wk     = (const float*)d_in[5];
    const float* bk     = (const float*)d_in[6];
    const float* wv     = (const float*)d_in[7];
    const float* bv     = (const float*)d_in[8];
    const float* wo     = (const float*)d_in[9];
    const float* bo     = (const float*)d_in[10];
    float* out = (float*)d_out;

    float *xb, *qkv, *bqkv, *wavg, *bavg;
    bf16 *ch, *cm, *cl, *ph, *pm, *pl;
    bf16 *wqkvh, *wqkvm, *wqkvl, *woh, *wom, *wol;
    cudaGetSymbolAddress((void**)&xb,    g_x);
    cudaGetSymbolAddress((void**)&ch,    g_ch);
    cudaGetSymbolAddress((void**)&cm,    g_cm);
    cudaGetSymbolAddress((void**)&cl,    g_cl);
    cudaGetSymbolAddress((void**)&qkv,   g_qkv);
    cudaGetSymbolAddress((void**)&ph,    g_ph);
    cudaGetSymbolAddress((void**)&pm,    g_pm);
    cudaGetSymbolAddress((void**)&pl,    g_pl);
    cudaGetSymbolAddress((void**)&wqkvh, g_wqkvh);
    cudaGetSymbolAddress((void**)&wqkvm, g_wqkvm);
    cudaGetSymbolAddress((void**)&wqkvl, g_wqkvl);
    cudaGetSymbolAddress((void**)&woh,   g_woh);
    cudaGetSymbolAddress((void**)&wom,   g_wom);
    cudaGetSymbolAddress((void**)&wol,   g_wol);
    cudaGetSymbolAddress((void**)&bqkv,  g_bqkv);
    cudaGetSymbolAddress((void**)&wavg,  g_wavg);
    cudaGetSymbolAddress((void**)&bavg,  g_bavg);

    cudaFuncSetAttribute(gemm_mma_kernel,
                         cudaFuncAttributeMaxDynamicSharedMemorySize, GEMM_SMEM);

    const size_t LPW = (size_t)Ld * Pd * Wd;   // 4M elements

    avg_conv_kernel<<<1, 64>>>(conv_w, conv_b, wavg, bavg);

    split3_kernel<<<1024, 256>>>(wq, wqkvh,           wqkvm,           wqkvl,           (int)(LPW / 8));
    split3_kernel<<<1024, 256>>>(wk, wqkvh + LPW,     wqkvm + LPW,     wqkvl + LPW,     (int)(LPW / 8));
    split3_kernel<<<1024, 256>>>(wv, wqkvh + 2 * LPW, wqkvm + 2 * LPW, wqkvl + 2 * LPW, (int)(LPW / 8));
    split3_kernel<<<1024, 256>>>(wo, woh,             wom,             wol,             (int)(LPW / 8));

    cudaMemcpyAsync(bqkv,               bq, Ld * Pd * 4, cudaMemcpyDeviceToDevice);
    cudaMemcpyAsync(bqkv + Ld * Pd,     bk, Ld * Pd * 4, cudaMemcpyDeviceToDevice);
    cudaMemcpyAsync(bqkv + 2 * Ld * Pd, bv, Ld * Pd * 4, cudaMemcpyDeviceToDevice);

    const size_t RP = (size_t)ROWS * Pd;

    for (int l = 0; l < Ld; l++) {
        const float* xin = (l == 0) ? x : xb;
        float* xout = (l == Ld - 1) ? out : xb;

        conv_row_kernel<<<ROWS, 256>>>(xin, ch, cm, cl, wavg + l * Kc, bavg + l);

        dim3 gq(Pd / 128, ROWS / 128, 3);
        gemm_mma_kernel<<<gq, 512, GEMM_SMEM>>>(
            ch, cm, cl,
            wqkvh + (size_t)l * Pd * Wd, wqkvm + (size_t)l * Pd * Wd, wqkvl + (size_t)l * Pd * Wd,
            bqkv + (size_t)l * Pd, qkv,
            Wd, Pd, LPW, (size_t)Ld * Pd, RP);

        fft_attn_kernel<<<ROWS, 256>>>(qkv, qkv + RP, qkv + 2 * RP, ph, pm, pl);

        dim3 go(Wd / 128, ROWS / 128, 1);
        gemm_mma_kernel<<<go, 512, GEMM_SMEM>>>(
            ph, pm, pl,
            woh + (size_t)l * Wd * Pd, wom + (size_t)l * Wd * Pd, wol + (size_t)l * Wd * Pd,
            bo + (size_t)l * Wd, xout,
            Pd, Wd, 0, 0, 0);
    }
}

// round 6
// speedup vs baseline: 1.6922x; 1.5842x over previous
#include <cuda_runtime.h>
#include <cuda_bf16.h>
#include <cstdint>

#define BSZ 32
#define CNT 128
#define Wd  2048
#define Pd  1024
#define Ed  8
#define Kc  25
#define Ld  2
#define ROWS (BSZ*CNT)   // 4096

typedef __nv_bfloat16 bf16;

// ---------------- scratch ----------------
__device__ float g_x[ROWS*Wd];                 // inter-layer activation (fp32)
__device__ bf16  g_ch[ROWS*Wd];                // conv out, bf16 h/m
__device__ bf16  g_cm[ROWS*Wd];
__device__ float g_qkv[3*ROWS*Pd];             // q,k,v (fp32, z-strided)
__device__ bf16  g_ph[ROWS*Pd];
__device__ bf16  g_pm[ROWS*Pd];
__device__ bf16  g_wqkvh[3*Ld*Pd*Wd];          // [z][layer][P][W]
__device__ bf16  g_wqkvm[3*Ld*Pd*Wd];
__device__ bf16  g_woh[Ld*Wd*Pd];
__device__ bf16  g_wom[Ld*Wd*Pd];
__device__ float g_bqkv[3*Ld*Pd];
__device__ float g_wavg[Ld*Kc];
__device__ float g_bavg[Ld];

// ---------------- helpers ----------------
__device__ __forceinline__ uint32_t smem_u32(const void* p) {
    uint32_t a;
    asm("{ .reg .u64 t; cvta.to.shared.u64 t, %1; cvt.u32.u64 %0, t; }" : "=r"(a) : "l"(p));
    return a;
}
__device__ __forceinline__ void cp16(uint32_t dst, const void* src) {
    asm volatile("cp.async.cg.shared.global [%0], [%1], 16;" :: "r"(dst), "l"(src));
}
__device__ __forceinline__ void split2(float x, bf16& h, bf16& m) {
    h = __float2bfloat16(x);
    m = __float2bfloat16(x - __bfloat162float(h));
}
__device__ __forceinline__ uint32_t pack2(bf16 a, bf16 b) {
    return (uint32_t)__bfloat16_as_ushort(a) | ((uint32_t)__bfloat16_as_ushort(b) << 16);
}

// ---------------- weight split fp32 -> 2x bf16 ----------------
__global__ void split2_kernel(const float* __restrict__ src, bf16* __restrict__ h,
                              bf16* __restrict__ m, int n8) {
    int i = blockIdx.x * blockDim.x + threadIdx.x;
    int stride = gridDim.x * blockDim.x;
    for (; i < n8; i += stride) {
        float4 v0 = ((const float4*)src)[2 * i];
        float4 v1 = ((const float4*)src)[2 * i + 1];
        float v[8] = {v0.x, v0.y, v0.z, v0.w, v1.x, v1.y, v1.z, v1.w};
        bf16 hh[8], mm_[8];
        #pragma unroll
        for (int e = 0; e < 8; e++) split2(v[e], hh[e], mm_[e]);
        uint4 u;
        u.x = pack2(hh[0], hh[1]); u.y = pack2(hh[2], hh[3]);
        u.z = pack2(hh[4], hh[5]); u.w = pack2(hh[6], hh[7]);
        ((uint4*)h)[i] = u;
        u.x = pack2(mm_[0], mm_[1]); u.y = pack2(mm_[2], mm_[3]);
        u.z = pack2(mm_[4], mm_[5]); u.w = pack2(mm_[6], mm_[7]);
        ((uint4*)m)[i] = u;
    }
}

// ---------------- avg conv weights ----------------
__global__ void avg_conv_kernel(const float* __restrict__ cw, const float* __restrict__ cb,
                                float* __restrict__ wavg, float* __restrict__ bavg) {
    int idx = threadIdx.x;
    if (idx < Ld * Kc) {
        int l = idx / Kc, kk = idx % Kc;
        float s = 0.f;
        #pragma unroll
        for (int e = 0; e < Ed; e++) s += cw[(l * Ed + e) * Kc + kk];
        wavg[idx] = s * (1.0f / Ed);
    }
    if (idx < Ld) {
        float s = 0.f;
        #pragma unroll
        for (int e = 0; e < Ed; e++) s += cb[idx * Ed + e];
        bavg[idx] = s * (1.0f / Ed);
    }
}

// ---------------- 1D conv, writes 2x bf16 ----------------
__global__ __launch_bounds__(256) void conv_row_kernel(
    const float* __restrict__ X, bf16* __restrict__ Yh, bf16* __restrict__ Ym,
    const float* __restrict__ wavg, const float* __restrict__ bavg)
{
    __shared__ float sx[Wd + Kc - 1];
    __shared__ float wsh[Kc];
    const int row = blockIdx.x;
    const int tid = threadIdx.x;
    const float* xr = X + (size_t)row * Wd;

    for (int i = tid; i < Wd + Kc - 1; i += 256) {
        int src = i - (Kc / 2);
        sx[i] = (src >= 0 && src < Wd) ? xr[src] : 0.0f;
    }
    if (tid < Kc) wsh[tid] = wavg[tid];
    __syncthreads();

    const float b = bavg[0];
    bf16* yh = Yh + (size_t)row * Wd;
    bf16* ym = Ym + (size_t)row * Wd;
    for (int h = tid; h < Wd; h += 256) {
        float s = b;
        #pragma unroll
        for (int k = 0; k < Kc; k++) s += sx[h + k] * wsh[k];
        bf16 sh, sm_;
        split2(s, sh, sm_);
        yh[h] = sh; ym[h] = sm_;
    }
}

// ---------------- bf16x3 mma.sync GEMM: C = A*B^T + bias ----------------
#define MMA16(cc, aa, bb) \
    asm volatile("mma.sync.aligned.m16n8k16.row.col.f32.bf16.bf16.f32 " \
        "{%0,%1,%2,%3},{%4,%5,%6,%7},{%8,%9},{%0,%1,%2,%3};" \
        : "+f"((cc)[0]), "+f"((cc)[1]), "+f"((cc)[2]), "+f"((cc)[3]) \
        : "r"((aa)[0]), "r"((aa)[1]), "r"((aa)[2]), "r"((aa)[3]), \
          "r"((bb)[0]), "r"((bb)[1]))

#define BK 32
#define TILE_W 2048            // 128 rows x 16 words (32 bf16), swizzled
#define STAGE_W (4*TILE_W)     // Ah,Am,Bh,Bm
#define NSTAGE 3
#define GEMM_SMEM (NSTAGE*STAGE_W*4)   // 98304 bytes

__global__ __launch_bounds__(512, 1) void gemm_mma_kernel(
    const bf16* __restrict__ Ah, const bf16* __restrict__ Am,
    const bf16* __restrict__ Bh, const bf16* __restrict__ Bm,
    const float* __restrict__ bias, float* __restrict__ C,
    int Kd, int N, size_t szB, size_t szBias, size_t szC)
{
    extern __shared__ uint32_t sm[];
    const uint32_t sbase = smem_u32(sm);
    const int z = blockIdx.z;
    Bh   += (size_t)z * szB;
    Bm   += (size_t)z * szB;
    bias += (size_t)z * szBias;
    C    += (size_t)z * szC;

    const int tid = threadIdx.x;
    const int wid = tid >> 5, lane = tid & 31;
    const int g = lane >> 2, t = lane & 3;
    const int wm = (wid >> 2) * 32;
    const int wn = (wid & 3) * 32;
    const int bm = blockIdx.y * 128, bn = blockIdx.x * 128;

    // cp.async mapping: one 16B transfer per tile per thread
    const int lrow = tid >> 2;          // 0..127
    const int c4 = tid & 3;             // 16B group within row
    const int sg = c4 ^ ((lrow >> 1) & 3);
    const uint32_t dstw = (uint32_t)(lrow * 16 + sg * 4);   // word index in tile

    const bf16* pAh = Ah + (size_t)(bm + lrow) * Kd + c4 * 8;
    const bf16* pAm = Am + (size_t)(bm + lrow) * Kd + c4 * 8;
    const bf16* pBh = Bh + (size_t)(bn + lrow) * Kd + c4 * 8;
    const bf16* pBm = Bm + (size_t)(bn + lrow) * Kd + c4 * 8;

    float acc[2][4][4];
    #pragma unroll
    for (int mt = 0; mt < 2; mt++)
        #pragma unroll
        for (int nt = 0; nt < 4; nt++)
            #pragma unroll
            for (int e = 0; e < 4; e++) acc[mt][nt][e] = 0.0f;

    const int NC = Kd / BK;

    #define ISSUE(s, kpos) do { \
        uint32_t _sb = sbase + (uint32_t)(s) * (STAGE_W * 4) + dstw * 4; \
        cp16(_sb,                   pAh + (kpos)); \
        cp16(_sb + TILE_W * 4,      pAm + (kpos)); \
        cp16(_sb + 2 * TILE_W * 4,  pBh + (kpos)); \
        cp16(_sb + 3 * TILE_W * 4,  pBm + (kpos)); \
        asm volatile("cp.async.commit_group;" ::: "memory"); \
    } while (0)

    ISSUE(0, 0);
    ISSUE(1, BK);

    for (int i = 0; i < NC; i++) {
        if (i + 1 < NC) asm volatile("cp.async.wait_group 1;" ::: "memory");
        else            asm volatile("cp.async.wait_group 0;" ::: "memory");
        __syncthreads();
        if (i + 2 < NC) {
            int s = i + 2; s = s - (s / 3) * 3;
            ISSUE(s, (i + 2) * BK);
        }

        int bsel = i - (i / 3) * 3;
        const uint32_t* sAh = sm + bsel * STAGE_W;
        const uint32_t* sAm = sAh + TILE_W;
        const uint32_t* sBh = sAm + TILE_W;
        const uint32_t* sBm = sBh + TILE_W;

        #pragma unroll
        for (int st = 0; st < 2; st++) {
            const int kb = st * 8;            // word-col base
            uint32_t ah[2][4], am_[2][4];
            uint32_t bh[4][2], bmr[4][2];
            #pragma unroll
            for (int mt = 0; mt < 2; mt++) {
                int r0 = wm + mt * 16 + g;
                int rx = ((r0 >> 1) & 3) << 2;
                int i0 = r0 * 16 + (kb ^ rx) + t;
                int i4 = r0 * 16 + ((kb + 4) ^ rx) + t;
                ah[mt][0] = sAh[i0]; ah[mt][1] = sAh[i0 + 128];
                ah[mt][2] = sAh[i4]; ah[mt][3] = sAh[i4 + 128];
                am_[mt][0] = sAm[i0]; am_[mt][1] = sAm[i0 + 128];
                am_[mt][2] = sAm[i4]; am_[mt][3] = sAm[i4 + 128];
            }
            #pragma unroll
            for (int nt = 0; nt < 4; nt++) {
                int rb = wn + nt * 8 + g;
                int rx = ((rb >> 1) & 3) << 2;
                int i0 = rb * 16 + (kb ^ rx) + t;
                int i4 = rb * 16 + ((kb + 4) ^ rx) + t;
                bh[nt][0]  = sBh[i0]; bh[nt][1]  = sBh[i4];
                bmr[nt][0] = sBm[i0]; bmr[nt][1] = sBm[i4];
            }
            #pragma unroll
            for (int mt = 0; mt < 2; mt++)
                #pragma unroll
                for (int nt = 0; nt < 4; nt++) {
                    MMA16(acc[mt][nt], ah[mt],  bh[nt]);
                    MMA16(acc[mt][nt], ah[mt],  bmr[nt]);
                    MMA16(acc[mt][nt], am_[mt], bh[nt]);
                }
        }
        __syncthreads();
    }
    #undef ISSUE

    // epilogue
    #pragma unroll
    for (int mt = 0; mt < 2; mt++) {
        #pragma unroll
        for (int nt = 0; nt < 4; nt++) {
            int col = bn + wn + nt * 8 + 2 * t;
            float b0 = __ldg(&bias[col]);
            float b1 = __ldg(&bias[col + 1]);
            float* p0 = C + (size_t)(bm + wm + mt * 16 + g) * N + col;
            float2 o0 = make_float2(acc[mt][nt][0] + b0, acc[mt][nt][1] + b1);
            float2 o1 = make_float2(acc[mt][nt][2] + b0, acc[mt][nt][3] + b1);
            *(float2*)p0 = o0;
            *(float2*)(p0 + 8 * N) = o1;
        }
    }
}

// ---------------- FFT attention (writes 2x bf16) ----------------
__device__ __forceinline__ void fft1024_stages(float2* s, int tid, float sign) {
    #pragma unroll
    for (int stage = 0; stage < 10; ++stage) {
        const int half = 1 << stage;
        #pragma unroll
        for (int r = 0; r < 2; ++r) {
            int b = tid + (r << 8);
            int pos = b & (half - 1);
            int i0 = ((b >> stage) << (stage + 1)) + pos;
            int i1 = i0 + half;
            float ang = sign * 3.14159265358979323846f * (float)pos / (float)half;
            float sn, cs;
            __sincosf(ang, &sn, &cs);
            float2 x1 = s[i1];
            float2 t = make_float2(x1.x * cs - x1.y * sn, x1.x * sn + x1.y * cs);
            float2 x0 = s[i0];
            s[i0] = make_float2(x0.x + t.x, x0.y + t.y);
            s[i1] = make_float2(x0.x - t.x, x0.y - t.y);
        }
        __syncthreads();
    }
}

__global__ __launch_bounds__(256) void fft_attn_kernel(
    const float* __restrict__ Q, const float* __restrict__ Kx,
    const float* __restrict__ V,
    bf16* __restrict__ Oh, bf16* __restrict__ Om)
{
    __shared__ float2 Z[1024];
    __shared__ float2 Aw[1024];
    const int row = blockIdx.x;
    const int tid = threadIdx.x;
    const float* qr = Q  + (size_t)row * Pd;
    const float* kr = Kx + (size_t)row * Pd;
    const float* vr = V  + (size_t)row * Pd;

    for (int i = tid; i < 1024; i += 256) {
        int rdx = __brev((unsigned)i) >> 22;
        Z[rdx] = make_float2(qr[i], kr[i]);
    }
    __syncthreads();
    fft1024_stages(Z, tid, -1.0f);

    const float inv_scale = 1.0f / 32.0f;
    for (int i = tid; i < 1024; i += 256) {
        float2 zj = Z[i];
        float2 zn = Z[(1024 - i) & 1023];
        float Qx = 0.5f * (zj.x + zn.x);
        float Qy = 0.5f * (zj.y - zn.y);
        float Kxr = 0.5f * (zj.y + zn.y);
        float Kyr = -0.5f * (zj.x - zn.x);
        float Ax = Kxr * Qx + Kyr * Qy;
        float Ay = Kyr * Qx - Kxr * Qy;
        Aw[i] = make_float2(Ax * inv_scale, Ay * inv_scale);
    }
    __syncthreads();

    for (int i = tid; i < 1024; i += 256) {
        int rdx = __brev((unsigned)i) >> 22;
        Z[rdx] = make_float2(vr[i], 0.0f);
    }
    __syncthreads();
    fft1024_stages(Z, tid, -1.0f);

    for (int i = tid; i < 1024; i += 256) {
        float2 vf = Z[i], a = Aw[i];
        Aw[i] = make_float2(vf.x * a.x - vf.y * a.y, vf.x * a.y + vf.y * a.x);
    }
    __syncthreads();

    for (int i = tid; i < 1024; i += 256) {
        int rdx = __brev((unsigned)i) >> 22;
        Z[rdx] = Aw[i];
    }
    __syncthreads();
    fft1024_stages(Z, tid, +1.0f);

    bf16* oh = Oh + (size_t)row * Pd;
    bf16* om = Om + (size_t)row * Pd;
    const float invN = 1.0f / 1024.0f;
    for (int i = tid; i < 1024; i += 256) {
        float s = Z[i].x * invN;
        bf16 sh, sm_;
        split2(s, sh, sm_);
        oh[i] = sh; om[i] = sm_;
    }
}

// ---------------- launch ----------------
extern "C" void kernel_launch(void* const* d_in, const int* in_sizes, int n_in,
                              void* d_out, int out_size) {
    (void)in_sizes; (void)n_in; (void)out_size;
    const float* x      = (const float*)d_in[0];
    const float* conv_w = (const float*)d_in[1];
    const float* conv_b = (const float*)d_in[2];
    const float* wq     = (const float*)d_in[3];
    const float* bq     = (const float*)d_in[4];
    const float* wk     = (const float*)d_in[5];
    const float* bk     = (const float*)d_in[6];
    const float* wv     = (const float*)d_in[7];
    const float* bv     = (const float*)d_in[8];
    const float* wo     = (const float*)d_in[9];
    const float* bo     = (const float*)d_in[10];
    float* out = (float*)d_out;

    float *xb, *qkv, *bqkv, *wavg, *bavg;
    bf16 *ch, *cm, *ph, *pm;
    bf16 *wqkvh, *wqkvm, *woh, *wom;
    cudaGetSymbolAddress((void**)&xb,    g_x);
    cudaGetSymbolAddress((void**)&ch,    g_ch);
    cudaGetSymbolAddress((void**)&cm,    g_cm);
    cudaGetSymbolAddress((void**)&qkv,   g_qkv);
    cudaGetSymbolAddress((void**)&ph,    g_ph);
    cudaGetSymbolAddress((void**)&pm,    g_pm);
    cudaGetSymbolAddress((void**)&wqkvh, g_wqkvh);
    cudaGetSymbolAddress((void**)&wqkvm, g_wqkvm);
    cudaGetSymbolAddress((void**)&woh,   g_woh);
    cudaGetSymbolAddress((void**)&wom,   g_wom);
    cudaGetSymbolAddress((void**)&bqkv,  g_bqkv);
    cudaGetSymbolAddress((void**)&wavg,  g_wavg);
    cudaGetSymbolAddress((void**)&bavg,  g_bavg);

    cudaFuncSetAttribute(gemm_mma_kernel,
                         cudaFuncAttributeMaxDynamicSharedMemorySize, GEMM_SMEM);

    const size_t LPW = (size_t)Ld * Pd * Wd;   // 4M elements

    avg_conv_kernel<<<1, 64>>>(conv_w, conv_b, wavg, bavg);

    split2_kernel<<<1024, 256>>>(wq, wqkvh,           wqkvm,           (int)(LPW / 8));
    split2_kernel<<<1024, 256>>>(wk, wqkvh + LPW,     wqkvm + LPW,     (int)(LPW / 8));
    split2_kernel<<<1024, 256>>>(wv, wqkvh + 2 * LPW, wqkvm + 2 * LPW, (int)(LPW / 8));
    split2_kernel<<<1024, 256>>>(wo, woh,             wom,             (int)(LPW / 8));

    cudaMemcpyAsync(bqkv,               bq, Ld * Pd * 4, cudaMemcpyDeviceToDevice);
    cudaMemcpyAsync(bqkv + Ld * Pd,     bk, Ld * Pd * 4, cudaMemcpyDeviceToDevice);
    cudaMemcpyAsync(bqkv + 2 * Ld * Pd, bv, Ld * Pd * 4, cudaMemcpyDeviceToDevice);

    const size_t RP = (size_t)ROWS * Pd;

    for (int l = 0; l < Ld; l++) {
        const float* xin = (l == 0) ? x : xb;
        float* xout = (l == Ld - 1) ? out : xb;

        conv_row_kernel<<<ROWS, 256>>>(xin, ch, cm, wavg + l * Kc, bavg + l);

        dim3 gq(Pd / 128, ROWS / 128, 3);
        gemm_mma_kernel<<<gq, 512, GEMM_SMEM>>>(
            ch, cm,
            wqkvh + (size_t)l * Pd * Wd, wqkvm + (size_t)l * Pd * Wd,
            bqkv + (size_t)l * Pd, qkv,
            Wd, Pd, LPW, (size_t)Ld * Pd, RP);

        fft_attn_kernel<<<ROWS, 256>>>(qkv, qkv + RP, qkv + 2 * RP, ph, pm);

        dim3 go(Wd / 128, ROWS / 128, 1);
        gemm_mma_kernel<<<go, 512, GEMM_SMEM>>>(
            ph, pm,
            woh + (size_t)l * Wd * Pd, wom + (size_t)l * Wd * Pd,
            bo + (size_t)l * Wd, xout,
            Pd, Wd, 0, 0, 0);
    }
}

// round 7
// speedup vs baseline: 1.8236x; 1.0776x over previous
#include <cuda_runtime.h>
#include <cuda_bf16.h>
#include <cstdint>

#define BSZ 32
#define CNT 128
#define Wd  2048
#define Pd  1024
#define Ed  8
#define Kc  25
#define Ld  2
#define ROWS (BSZ*CNT)   // 4096

typedef __nv_bfloat16 bf16;

// ---------------- scratch ----------------
__device__ float g_x[ROWS*Wd];
__device__ bf16  g_ch[ROWS*Wd];
__device__ bf16  g_cm[ROWS*Wd];
__device__ float g_qkv[3*ROWS*Pd];
__device__ bf16  g_ph[ROWS*Pd];
__device__ bf16  g_pm[ROWS*Pd];
__device__ bf16  g_wqkvh[3*Ld*Pd*Wd];
__device__ bf16  g_wqkvm[3*Ld*Pd*Wd];
__device__ bf16  g_woh[Ld*Wd*Pd];
__device__ bf16  g_wom[Ld*Wd*Pd];
__device__ float g_bqkv[3*Ld*Pd];
__device__ float g_wavg[Ld*Kc];
__device__ float g_bavg[Ld];

// ---------------- helpers ----------------
__device__ __forceinline__ uint32_t smem_u32(const void* p) {
    uint32_t a;
    asm("{ .reg .u64 t; cvta.to.shared.u64 t, %1; cvt.u32.u64 %0, t; }" : "=r"(a) : "l"(p));
    return a;
}
__device__ __forceinline__ void cp16(uint32_t dst, const void* src) {
    asm volatile("cp.async.cg.shared.global [%0], [%1], 16;" :: "r"(dst), "l"(src));
}
__device__ __forceinline__ void split2(float x, bf16& h, bf16& m) {
    h = __float2bfloat16(x);
    m = __float2bfloat16(x - __bfloat162float(h));
}
__device__ __forceinline__ uint32_t pack2(bf16 a, bf16 b) {
    return (uint32_t)__bfloat16_as_ushort(a) | ((uint32_t)__bfloat16_as_ushort(b) << 16);
}

// ---------------- weight split fp32 -> 2x bf16 ----------------
__global__ void split2_kernel(const float* __restrict__ src, bf16* __restrict__ h,
                              bf16* __restrict__ m, int n8) {
    int i = blockIdx.x * blockDim.x + threadIdx.x;
    int stride = gridDim.x * blockDim.x;
    for (; i < n8; i += stride) {
        float4 v0 = ((const float4*)src)[2 * i];
        float4 v1 = ((const float4*)src)[2 * i + 1];
        float v[8] = {v0.x, v0.y, v0.z, v0.w, v1.x, v1.y, v1.z, v1.w};
        bf16 hh[8], mm_[8];
        #pragma unroll
        for (int e = 0; e < 8; e++) split2(v[e], hh[e], mm_[e]);
        uint4 u;
        u.x = pack2(hh[0], hh[1]); u.y = pack2(hh[2], hh[3]);
        u.z = pack2(hh[4], hh[5]); u.w = pack2(hh[6], hh[7]);
        ((uint4*)h)[i] = u;
        u.x = pack2(mm_[0], mm_[1]); u.y = pack2(mm_[2], mm_[3]);
        u.z = pack2(mm_[4], mm_[5]); u.w = pack2(mm_[6], mm_[7]);
        ((uint4*)m)[i] = u;
    }
}

// ---------------- avg conv weights ----------------
__global__ void avg_conv_kernel(const float* __restrict__ cw, const float* __restrict__ cb,
                                float* __restrict__ wavg, float* __restrict__ bavg) {
    int idx = threadIdx.x;
    if (idx < Ld * Kc) {
        int l = idx / Kc, kk = idx % Kc;
        float s = 0.f;
        #pragma unroll
        for (int e = 0; e < Ed; e++) s += cw[(l * Ed + e) * Kc + kk];
        wavg[idx] = s * (1.0f / Ed);
    }
    if (idx < Ld) {
        float s = 0.f;
        #pragma unroll
        for (int e = 0; e < Ed; e++) s += cb[idx * Ed + e];
        bavg[idx] = s * (1.0f / Ed);
    }
}

// ---------------- 1D conv, writes 2x bf16 ----------------
__global__ __launch_bounds__(256) void conv_row_kernel(
    const float* __restrict__ X, bf16* __restrict__ Yh, bf16* __restrict__ Ym,
    const float* __restrict__ wavg, const float* __restrict__ bavg)
{
    __shared__ float sx[Wd + Kc - 1];
    __shared__ float wsh[Kc];
    const int row = blockIdx.x;
    const int tid = threadIdx.x;
    const float* xr = X + (size_t)row * Wd;

    for (int i = tid; i < Wd + Kc - 1; i += 256) {
        int src = i - (Kc / 2);
        sx[i] = (src >= 0 && src < Wd) ? xr[src] : 0.0f;
    }
    if (tid < Kc) wsh[tid] = wavg[tid];
    __syncthreads();

    const float b = bavg[0];
    bf16* yh = Yh + (size_t)row * Wd;
    bf16* ym = Ym + (size_t)row * Wd;
    for (int h = tid; h < Wd; h += 256) {
        float s = b;
        #pragma unroll
        for (int k = 0; k < Kc; k++) s += sx[h + k] * wsh[k];
        bf16 sh, sm_;
        split2(s, sh, sm_);
        yh[h] = sh; ym[h] = sm_;
    }
}

// ---------------- bf16x3 mma.sync GEMM, 128x256 CTA tile, 64x64 warp tile ----------------
#define MMA16(cc, aa, bb) \
    asm volatile("mma.sync.aligned.m16n8k16.row.col.f32.bf16.bf16.f32 " \
        "{%0,%1,%2,%3},{%4,%5,%6,%7},{%8,%9},{%0,%1,%2,%3};" \
        : "+f"((cc)[0]), "+f"((cc)[1]), "+f"((cc)[2]), "+f"((cc)[3]) \
        : "r"((aa)[0]), "r"((aa)[1]), "r"((aa)[2]), "r"((aa)[3]), \
          "r"((bb)[0]), "r"((bb)[1]))

#define BK 32
#define ATILE_W 2048           // 128 rows x 16 words
#define BTILE_W 4096           // 256 rows x 16 words
#define STAGE_W (2*ATILE_W + 2*BTILE_W)   // 12288 words = 48KB
#define NSTAGE 3
#define GEMM_SMEM (NSTAGE*STAGE_W*4)      // 147456 bytes

__global__ __launch_bounds__(256, 1) void gemm_mma_kernel(
    const bf16* __restrict__ Ah, const bf16* __restrict__ Am,
    const bf16* __restrict__ Bh, const bf16* __restrict__ Bm,
    const float* __restrict__ bias, float* __restrict__ C,
    int Kd, int N, size_t szB, size_t szBias, size_t szC)
{
    extern __shared__ uint32_t sm[];
    const uint32_t sbase = smem_u32(sm);
    const int z = blockIdx.z;
    Bh   += (size_t)z * szB;
    Bm   += (size_t)z * szB;
    bias += (size_t)z * szBias;
    C    += (size_t)z * szC;

    const int tid = threadIdx.x;
    const int wid = tid >> 5, lane = tid & 31;
    const int g = lane >> 2, t = lane & 3;
    const int wm = (wid >> 2) * 64;       // 2 warp-rows
    const int wn = (wid & 3) * 64;        // 4 warp-cols
    const int bm = blockIdx.y * 128, bn = blockIdx.x * 256;

    // cp.async mapping
    // A plane: 512 groups (128 rows x 4); thread handles gidx = tid, tid+256
    const int a0r = tid >> 2,            a0c = tid & 3;
    const int a1r = (tid + 256) >> 2,    a1c = tid & 3;
    const uint32_t a0d = (uint32_t)(a0r * 16 + ((a0c ^ ((a0r >> 1) & 3)) << 2)) * 4;
    const uint32_t a1d = (uint32_t)(a1r * 16 + ((a1c ^ ((a1r >> 1) & 3)) << 2)) * 4;
    const bf16* a0h = Ah + (size_t)(bm + a0r) * Kd + a0c * 8;
    const bf16* a0m = Am + (size_t)(bm + a0r) * Kd + a0c * 8;
    const bf16* a1h = Ah + (size_t)(bm + a1r) * Kd + a1c * 8;
    const bf16* a1m = Am + (size_t)(bm + a1r) * Kd + a1c * 8;
    // B plane: 1024 groups (256 rows x 4); thread handles tid + j*256, j<4
    uint32_t bd[4];
    const bf16 *bhp[4], *bmp[4];
    #pragma unroll
    for (int j = 0; j < 4; j++) {
        int gi = tid + j * 256;
        int br = gi >> 2, bc = gi & 3;
        bd[j] = (uint32_t)(br * 16 + ((bc ^ ((br >> 1) & 3)) << 2)) * 4;
        bhp[j] = Bh + (size_t)(bn + br) * Kd + bc * 8;
        bmp[j] = Bm + (size_t)(bn + br) * Kd + bc * 8;
    }

    float acc[4][8][4];
    #pragma unroll
    for (int mt = 0; mt < 4; mt++)
        #pragma unroll
        for (int nt = 0; nt < 8; nt++)
            #pragma unroll
            for (int e = 0; e < 4; e++) acc[mt][nt][e] = 0.0f;

    const int NC = Kd / BK;

    #define ISSUE(s, kpos) do { \
        uint32_t _sb = sbase + (uint32_t)(s) * (STAGE_W * 4); \
        cp16(_sb + a0d,                  a0h + (kpos)); \
        cp16(_sb + a1d,                  a1h + (kpos)); \
        cp16(_sb + ATILE_W * 4 + a0d,    a0m + (kpos)); \
        cp16(_sb + ATILE_W * 4 + a1d,    a1m + (kpos)); \
        uint32_t _bb = _sb + 2 * ATILE_W * 4; \
        cp16(_bb + bd[0],                bhp[0] + (kpos)); \
        cp16(_bb + bd[1],                bhp[1] + (kpos)); \
        cp16(_bb + bd[2],                bhp[2] + (kpos)); \
        cp16(_bb + bd[3],                bhp[3] + (kpos)); \
        cp16(_bb + BTILE_W * 4 + bd[0],  bmp[0] + (kpos)); \
        cp16(_bb + BTILE_W * 4 + bd[1],  bmp[1] + (kpos)); \
        cp16(_bb + BTILE_W * 4 + bd[2],  bmp[2] + (kpos)); \
        cp16(_bb + BTILE_W * 4 + bd[3],  bmp[3] + (kpos)); \
        asm volatile("cp.async.commit_group;" ::: "memory"); \
    } while (0)

    ISSUE(0, 0);
    ISSUE(1, BK);

    for (int i = 0; i < NC; i++) {
        if (i + 1 < NC) asm volatile("cp.async.wait_group 1;" ::: "memory");
        else            asm volatile("cp.async.wait_group 0;" ::: "memory");
        __syncthreads();
        if (i + 2 < NC) {
            int s = i + 2; s = s - (s / 3) * 3;
            ISSUE(s, (i + 2) * BK);
        }

        int bsel = i - (i / 3) * 3;
        const uint32_t* sAh = sm + bsel * STAGE_W;
        const uint32_t* sAm = sAh + ATILE_W;
        const uint32_t* sBh = sAm + ATILE_W;
        const uint32_t* sBm = sBh + BTILE_W;

        #pragma unroll
        for (int st = 0; st < 2; st++) {
            const int kb = st * 8;
            uint32_t bh[8][2], bmr[8][2];
            #pragma unroll
            for (int nt = 0; nt < 8; nt++) {
                int rb = wn + nt * 8 + g;
                int rx = ((rb >> 1) & 3) << 2;
                int i0 = rb * 16 + (kb ^ rx) + t;
                int i4 = rb * 16 + ((kb + 4) ^ rx) + t;
                bh[nt][0]  = sBh[i0]; bh[nt][1]  = sBh[i4];
                bmr[nt][0] = sBm[i0]; bmr[nt][1] = sBm[i4];
            }
            #pragma unroll
            for (int mt = 0; mt < 4; mt++) {
                int r0 = wm + mt * 16 + g;
                int rx = ((r0 >> 1) & 3) << 2;
                int i0 = r0 * 16 + (kb ^ rx) + t;
                int i4 = r0 * 16 + ((kb + 4) ^ rx) + t;
                uint32_t ah[4], am_[4];
                ah[0] = sAh[i0]; ah[1] = sAh[i0 + 128];
                ah[2] = sAh[i4]; ah[3] = sAh[i4 + 128];
                am_[0] = sAm[i0]; am_[1] = sAm[i0 + 128];
                am_[2] = sAm[i4]; am_[3] = sAm[i4 + 128];
                #pragma unroll
                for (int nt = 0; nt < 8; nt++) {
                    MMA16(acc[mt][nt], ah,  bh[nt]);
                    MMA16(acc[mt][nt], ah,  bmr[nt]);
                    MMA16(acc[mt][nt], am_, bh[nt]);
                }
            }
        }
        __syncthreads();
    }
    #undef ISSUE

    // epilogue
    #pragma unroll
    for (int mt = 0; mt < 4; mt++) {
        #pragma unroll
        for (int nt = 0; nt < 8; nt++) {
            int col = bn + wn + nt * 8 + 2 * t;
            float b0 = __ldg(&bias[col]);
            float b1 = __ldg(&bias[col + 1]);
            float* p0 = C + (size_t)(bm + wm + mt * 16 + g) * N + col;
            float2 o0 = make_float2(acc[mt][nt][0] + b0, acc[mt][nt][1] + b1);
            float2 o1 = make_float2(acc[mt][nt][2] + b0, acc[mt][nt][3] + b1);
            *(float2*)p0 = o0;
            *(float2*)(p0 + 8 * N) = o1;
        }
    }
}

// ---------------- FFT attention (twiddle table, writes 2x bf16) ----------------
__device__ __forceinline__ void fft1024_stages(float2* s, const float2* Tw, int tid, bool inv) {
    #pragma unroll
    for (int stage = 0; stage < 10; ++stage) {
        const int half = 1 << stage;
        #pragma unroll
        for (int r = 0; r < 2; ++r) {
            int b = tid + (r << 8);
            int pos = b & (half - 1);
            int i0 = ((b >> stage) << (stage + 1)) + pos;
            int i1 = i0 + half;
            float2 w = Tw[pos << (9 - stage)];
            float cs = w.x;
            float sn = inv ? -w.y : w.y;
            float2 x1 = s[i1];
            float2 t = make_float2(x1.x * cs - x1.y * sn, x1.x * sn + x1.y * cs);
            float2 x0 = s[i0];
            s[i0] = make_float2(x0.x + t.x, x0.y + t.y);
            s[i1] = make_float2(x0.x - t.x, x0.y - t.y);
        }
        __syncthreads();
    }
}

__global__ __launch_bounds__(256) void fft_attn_kernel(
    const float* __restrict__ Q, const float* __restrict__ Kx,
    const float* __restrict__ V,
    bf16* __restrict__ Oh, bf16* __restrict__ Om)
{
    __shared__ float2 Z[1024];
    __shared__ float2 Aw[1024];
    __shared__ float2 Tw[512];
    const int row = blockIdx.x;
    const int tid = threadIdx.x;
    const float* qr = Q  + (size_t)row * Pd;
    const float* kr = Kx + (size_t)row * Pd;
    const float* vr = V  + (size_t)row * Pd;

    for (int j = tid; j < 512; j += 256) {
        float sn, cs;
        __sincosf(-3.14159265358979323846f * (float)j / 512.0f, &sn, &cs);
        Tw[j] = make_float2(cs, sn);
    }

    for (int i = tid; i < 1024; i += 256) {
        int rdx = __brev((unsigned)i) >> 22;
        Z[rdx] = make_float2(qr[i], kr[i]);
    }
    __syncthreads();
    fft1024_stages(Z, Tw, tid, false);

    const float inv_scale = 1.0f / 32.0f;
    for (int i = tid; i < 1024; i += 256) {
        float2 zj = Z[i];
        float2 zn = Z[(1024 - i) & 1023];
        float Qx = 0.5f * (zj.x + zn.x);
        float Qy = 0.5f * (zj.y - zn.y);
        float Kxr = 0.5f * (zj.y + zn.y);
        float Kyr = -0.5f * (zj.x - zn.x);
        float Ax = Kxr * Qx + Kyr * Qy;
        float Ay = Kyr * Qx - Kxr * Qy;
        Aw[i] = make_float2(Ax * inv_scale, Ay * inv_scale);
    }
    __syncthreads();

    for (int i = tid; i < 1024; i += 256) {
        int rdx = __brev((unsigned)i) >> 22;
        Z[rdx] = make_float2(vr[i], 0.0f);
    }
    __syncthreads();
    fft1024_stages(Z, Tw, tid, false);

    for (int i = tid; i < 1024; i += 256) {
        float2 vf = Z[i], a = Aw[i];
        Aw[i] = make_float2(vf.x * a.x - vf.y * a.y, vf.x * a.y + vf.y * a.x);
    }
    __syncthreads();

    for (int i = tid; i < 1024; i += 256) {
        int rdx = __brev((unsigned)i) >> 22;
        Z[rdx] = Aw[i];
    }
    __syncthreads();
    fft1024_stages(Z, Tw, tid, true);

    bf16* oh = Oh + (size_t)row * Pd;
    bf16* om = Om + (size_t)row * Pd;
    const float invN = 1.0f / 1024.0f;
    for (int i = tid; i < 1024; i += 256) {
        float s = Z[i].x * invN;
        bf16 sh, sm_;
        split2(s, sh, sm_);
        oh[i] = sh; om[i] = sm_;
    }
}

// ---------------- launch ----------------
extern "C" void kernel_launch(void* const* d_in, const int* in_sizes, int n_in,
                              void* d_out, int out_size) {
    (void)in_sizes; (void)n_in; (void)out_size;
    const float* x      = (const float*)d_in[0];
    const float* conv_w = (const float*)d_in[1];
    const float* conv_b = (const float*)d_in[2];
    const float* wq     = (const float*)d_in[3];
    const float* bq     = (const float*)d_in[4];
    const float* wk     = (const float*)d_in[5];
    const float* bk     = (const float*)d_in[6];
    const float* wv     = (const float*)d_in[7];
    const float* bv     = (const float*)d_in[8];
    const float* wo     = (const float*)d_in[9];
    const float* bo     = (const float*)d_in[10];
    float* out = (float*)d_out;

    float *xb, *qkv, *bqkv, *wavg, *bavg;
    bf16 *ch, *cm, *ph, *pm;
    bf16 *wqkvh, *wqkvm, *woh, *wom;
    cudaGetSymbolAddress((void**)&xb,    g_x);
    cudaGetSymbolAddress((void**)&ch,    g_ch);
    cudaGetSymbolAddress((void**)&cm,    g_cm);
    cudaGetSymbolAddress((void**)&qkv,   g_qkv);
    cudaGetSymbolAddress((void**)&ph,    g_ph);
    cudaGetSymbolAddress((void**)&pm,    g_pm);
    cudaGetSymbolAddress((void**)&wqkvh, g_wqkvh);
    cudaGetSymbolAddress((void**)&wqkvm, g_wqkvm);
    cudaGetSymbolAddress((void**)&woh,   g_woh);
    cudaGetSymbolAddress((void**)&wom,   g_wom);
    cudaGetSymbolAddress((void**)&bqkv,  g_bqkv);
    cudaGetSymbolAddress((void**)&wavg,  g_wavg);
    cudaGetSymbolAddress((void**)&bavg,  g_bavg);

    cudaFuncSetAttribute(gemm_mma_kernel,
                         cudaFuncAttributeMaxDynamicSharedMemorySize, GEMM_SMEM);

    const size_t LPW = (size_t)Ld * Pd * Wd;   // 4M elements

    avg_conv_kernel<<<1, 64>>>(conv_w, conv_b, wavg, bavg);

    split2_kernel<<<1024, 256>>>(wq, wqkvh,           wqkvm,           (int)(LPW / 8));
    split2_kernel<<<1024, 256>>>(wk, wqkvh + LPW,     wqkvm + LPW,     (int)(LPW / 8));
    split2_kernel<<<1024, 256>>>(wv, wqkvh + 2 * LPW, wqkvm + 2 * LPW, (int)(LPW / 8));
    split2_kernel<<<1024, 256>>>(wo, woh,             wom,             (int)(LPW / 8));

    cudaMemcpyAsync(bqkv,               bq, Ld * Pd * 4, cudaMemcpyDeviceToDevice);
    cudaMemcpyAsync(bqkv + Ld * Pd,     bk, Ld * Pd * 4, cudaMemcpyDeviceToDevice);
    cudaMemcpyAsync(bqkv + 2 * Ld * Pd, bv, Ld * Pd * 4, cudaMemcpyDeviceToDevice);

    const size_t RP = (size_t)ROWS * Pd;

    for (int l = 0; l < Ld; l++) {
        const float* xin = (l == 0) ? x : xb;
        float* xout = (l == Ld - 1) ? out : xb;

        conv_row_kernel<<<ROWS, 256>>>(xin, ch, cm, wavg + l * Kc, bavg + l);

        dim3 gq(Pd / 256, ROWS / 128, 3);     // (4, 32, 3)
        gemm_mma_kernel<<<gq, 256, GEMM_SMEM>>>(
            ch, cm,
            wqkvh + (size_t)l * Pd * Wd, wqkvm + (size_t)l * Pd * Wd,
            bqkv + (size_t)l * Pd, qkv,
            Wd, Pd, LPW, (size_t)Ld * Pd, RP);

        fft_attn_kernel<<<ROWS, 256>>>(qkv, qkv + RP, qkv + 2 * RP, ph, pm);

        dim3 go(Wd / 256, ROWS / 128, 1);     // (8, 32, 1)
        gemm_mma_kernel<<<go, 256, GEMM_SMEM>>>(
            ph, pm,
            woh + (size_t)l * Wd * Pd, wom + (size_t)l * Wd * Pd,
            bo + (size_t)l * Wd, xout,
            Pd, Wd, 0, 0, 0);
    }
}